// round 16
// baseline (speedup 1.0000x reference)
#include <cuda_runtime.h>
#include <cuda_fp16.h>
#include <math.h>
#include <stdint.h>

#define B_DIM 2
#define S_DIM 8192
#define E_DIM 128

// fp16 fragment-permuted scratch (uint4 = 8 halves):
// g_Qp: per m-tile (16 q rows): [kk 0..7][lane] -> A-frag m16n8k16 {a0,a1,a2,a3}
// g_Kp: per kv-tile: [j 0..15][kkp 0..3][lane] -> K B-frags (n=kv, k=E)
// g_Vp: per kv-tile: [j(e) 0..15][kkp(kv) 0..3][lane] -> V B-frags (n=E, k=kv)
__device__ uint4 g_Qp[B_DIM * S_DIM * E_DIM / 8];
__device__ uint4 g_Kp[B_DIM * S_DIM * E_DIM / 8];
__device__ uint4 g_Vp[B_DIM * S_DIM * E_DIM / 8];

__device__ __forceinline__ uint32_t smem_to_u32(const void* p) {
    uint32_t a;
    asm("{ .reg .u64 t; cvta.to.shared.u64 t, %1; cvt.u32.u64 %0, t; }" : "=r"(a) : "l"(p));
    return a;
}
__device__ __forceinline__ void mma_f16(float* d, const uint32_t* a, const uint32_t* b) {
    asm volatile(
        "mma.sync.aligned.m16n8k16.row.col.f32.f16.f16.f32 "
        "{%0,%1,%2,%3}, {%4,%5,%6,%7}, {%8,%9}, {%0,%1,%2,%3};"
        : "+f"(d[0]), "+f"(d[1]), "+f"(d[2]), "+f"(d[3])
        : "r"(a[0]), "r"(a[1]), "r"(a[2]), "r"(a[3]), "r"(b[0]), "r"(b[1]));
}
__device__ __forceinline__ uint32_t pack_h2(float lo, float hi) {
    __half2 h = __floats2half2_rn(lo, hi);
    return *reinterpret_cast<uint32_t*>(&h);
}
// exp2 on packed fp16 pair: one MUFU op for two values
__device__ __forceinline__ uint32_t ex2_h2(float lo, float hi) {
    __half2 s = __floats2half2_rn(lo, hi);
    uint32_t si = *reinterpret_cast<uint32_t*>(&s);
    uint32_t r;
    asm("ex2.approx.f16x2 %0, %1;" : "=r"(r) : "r"(si));
    return r;
}
__device__ __forceinline__ void cp_async16(uint32_t saddr, const void* g) {
    asm volatile("cp.async.cg.shared.global [%0], [%1], 16;" :: "r"(saddr), "l"(g));
}
#define CP_COMMIT() asm volatile("cp.async.commit_group;" ::: "memory")
#define CP_WAIT1()  asm volatile("cp.async.wait_group 1;" ::: "memory")

// ============ fused projection: Q,K,V in ONE CTA (single wave) =============
// grid = (B*S)/128 = 128 CTAs. Per CTA: X tile -> SMEM once, Xa frags in
// registers once, then 3 phases {build Wf, 128 warp-MMAs, epilogue}.
__global__ __launch_bounds__(256) void proj_kernel(
    const float* __restrict__ x,
    const float* __restrict__ Wq, const float* __restrict__ bq,
    const float* __restrict__ Wk, const float* __restrict__ bk,
    const float* __restrict__ Wv, const float* __restrict__ bvp)
{
    extern __shared__ float sm[];
    float* nat = sm;                           // [s 128][e, stride 132] fp32
    uint4* Wf  = (uint4*)(sm + 128 * 132);     // [jn 16][kkp 4][lane 32]

    const int t = threadIdx.x;
    const float kscale = 0.08838834764831845f * 1.4426950408889634f;

    const int row_base = blockIdx.x * 128;
    const int lane = t & 31, wid = t >> 5;
    const int rr = lane >> 2, cc = lane & 3;

    #pragma unroll
    for (int i = 0; i < 16; ++i) {
        const int f = t + i * 256;
        const int row = f >> 5, c4 = (f & 31) * 4;
        *(float4*)&nat[row * 132 + c4] =
            *(const float4*)&x[(size_t)(row_base + row) * E_DIM + c4];
    }
    __syncthreads();

    uint32_t Xa[8][4];
    const int r0 = 16 * wid + rr;
    #pragma unroll
    for (int kk = 0; kk < 8; ++kk) {
        const int e0 = 16 * kk + 2 * cc;
        Xa[kk][0] = pack_h2(nat[r0 * 132 + e0],           nat[r0 * 132 + e0 + 1]);
        Xa[kk][1] = pack_h2(nat[(r0 + 8) * 132 + e0],     nat[(r0 + 8) * 132 + e0 + 1]);
        Xa[kk][2] = pack_h2(nat[r0 * 132 + e0 + 8],       nat[r0 * 132 + e0 + 9]);
        Xa[kk][3] = pack_h2(nat[(r0 + 8) * 132 + e0 + 8], nat[(r0 + 8) * 132 + e0 + 9]);
    }

    __half* Vst = (__half*)sm;   // overlays nat (dead after Xa build)
    const int b = row_base / S_DIM, s_in = row_base % S_DIM, kt = s_in >> 7;
    const size_t tbase = (size_t)(b * 64 + kt) * 2048;

    const float* Ws[3] = {Wq, Wk, Wv};
    const float* bs[3] = {bq, bk, bvp};

    #pragma unroll 1
    for (int which = 0; which < 3; ++which) {
        const float* __restrict__ W  = Ws[which];
        const float* __restrict__ bb = bs[which];

        __syncthreads();
        #pragma unroll
        for (int jj = 0; jj < 2; ++jj) {
            const int jn = 2 * wid + jj;
            const int n0 = 8 * jn + rr;
            #pragma unroll
            for (int kkp = 0; kkp < 4; ++kkp) {
                const int e0 = 32 * kkp + 2 * cc;
                uint4 v;
                v.x = pack_h2(W[n0 * 128 + e0],      W[n0 * 128 + e0 + 1]);
                v.y = pack_h2(W[n0 * 128 + e0 + 8],  W[n0 * 128 + e0 + 9]);
                v.z = pack_h2(W[n0 * 128 + e0 + 16], W[n0 * 128 + e0 + 17]);
                v.w = pack_h2(W[n0 * 128 + e0 + 24], W[n0 * 128 + e0 + 25]);
                Wf[(jn * 4 + kkp) * 32 + lane] = v;
            }
        }
        __syncthreads();

        #pragma unroll
        for (int jg = 0; jg < 4; ++jg) {
            float f4[4][4];
            #pragma unroll
            for (int jl = 0; jl < 4; ++jl)
                #pragma unroll
                for (int q = 0; q < 4; ++q) f4[jl][q] = 0.0f;

            #pragma unroll
            for (int jl = 0; jl < 4; ++jl) {
                const int jn = 4 * jg + jl;
                #pragma unroll
                for (int kkp = 0; kkp < 4; ++kkp) {
                    uint4 bv = Wf[(jn * 4 + kkp) * 32 + lane];
                    uint32_t b0[2] = {bv.x, bv.y}, b1[2] = {bv.z, bv.w};
                    mma_f16(f4[jl], Xa[2 * kkp], b0);
                    mma_f16(f4[jl], Xa[2 * kkp + 1], b1);
                }
                const float2 bias = *(const float2*)&bb[8 * jn + 2 * cc];
                f4[jl][0] += bias.x; f4[jl][1] += bias.y;
                f4[jl][2] += bias.x; f4[jl][3] += bias.y;
            }

            if (which == 0) {
                #pragma unroll
                for (int jl = 0; jl < 4; ++jl)
                    #pragma unroll
                    for (int q = 0; q < 4; ++q) f4[jl][q] *= kscale;
                const size_t mbase = ((size_t)(row_base >> 4) + (size_t)wid) * 256;
                uint4 v0, v1;
                v0.x = pack_h2(f4[0][0], f4[0][1]);
                v0.y = pack_h2(f4[0][2], f4[0][3]);
                v0.z = pack_h2(f4[1][0], f4[1][1]);
                v0.w = pack_h2(f4[1][2], f4[1][3]);
                g_Qp[mbase + (size_t)(2 * jg) * 32 + lane] = v0;
                v1.x = pack_h2(f4[2][0], f4[2][1]);
                v1.y = pack_h2(f4[2][2], f4[2][3]);
                v1.z = pack_h2(f4[3][0], f4[3][1]);
                v1.w = pack_h2(f4[3][2], f4[3][3]);
                g_Qp[mbase + (size_t)(2 * jg + 1) * 32 + lane] = v1;
            } else if (which == 1) {
                uint4 v0, v1;
                v0.x = pack_h2(f4[0][0], f4[0][1]);
                v0.y = pack_h2(f4[1][0], f4[1][1]);
                v0.z = pack_h2(f4[2][0], f4[2][1]);
                v0.w = pack_h2(f4[3][0], f4[3][1]);
                g_Kp[tbase + (size_t)(2 * wid) * 128 + jg * 32 + lane] = v0;
                v1.x = pack_h2(f4[0][2], f4[0][3]);
                v1.y = pack_h2(f4[1][2], f4[1][3]);
                v1.z = pack_h2(f4[2][2], f4[2][3]);
                v1.w = pack_h2(f4[3][2], f4[3][3]);
                g_Kp[tbase + (size_t)(2 * wid + 1) * 128 + jg * 32 + lane] = v1;
            } else {
                #pragma unroll
                for (int jl = 0; jl < 4; ++jl) {
                    const int e0 = 8 * (4 * jg + jl) + 2 * cc;
                    Vst[e0 * 132 + r0]           = __float2half_rn(f4[jl][0]);
                    Vst[(e0 + 1) * 132 + r0]     = __float2half_rn(f4[jl][1]);
                    Vst[e0 * 132 + r0 + 8]       = __float2half_rn(f4[jl][2]);
                    Vst[(e0 + 1) * 132 + r0 + 8] = __float2half_rn(f4[jl][3]);
                }
            }
        }
    }

    __syncthreads();
    #pragma unroll
    for (int jj = 0; jj < 2; ++jj) {
        const int j = 2 * wid + jj;
        const int erow = 8 * j + rr;
        #pragma unroll
        for (int kkp = 0; kkp < 4; ++kkp) {
            const int s0 = 32 * kkp + 2 * cc;
            const int s1 = s0 + 16;
            uint4 v;
            v.x = *(const uint32_t*)&Vst[erow * 132 + s0];
            v.y = *(const uint32_t*)&Vst[erow * 132 + s0 + 8];
            v.z = *(const uint32_t*)&Vst[erow * 132 + s1];
            v.w = *(const uint32_t*)&Vst[erow * 132 + s1 + 8];
            g_Vp[tbase + (size_t)j * 128 + kkp * 32 + lane] = v;
        }
    }
}

// ============ fp16 flash attention: 3-stage pipeline, warp-staggered ======
// grid (S/128, B), 256 threads = 8 warps; warp w owns m-tile w (16 q rows) x
// all 128 kv columns. Q/P in registers, rsum on tensor pipe.
// NEW: odd warps process kv-chunks in order 2,3,0,1 so the two warps on each
// SMSP anti-correlate their MUFU(exp)/pack pockets with partner MMA phases.
__device__ __forceinline__ void prefetch_tile(uint32_t sdst, const uint4* ksrc,
                                              const uint4* vsrc, int t) {
    #pragma unroll
    for (int i = 0; i < 8; ++i) {
        const int s = t + i * 256;
        cp_async16(sdst + s * 16, ksrc + s);
        cp_async16(sdst + 32768 + s * 16, vsrc + s);
    }
}

__global__ __launch_bounds__(256, 1) void attn_mma_kernel(float* __restrict__ out)
{
    extern __shared__ uint4 sbuf[];   // 3 stages x 4096 uint4
    const int t = threadIdx.x;
    const int lane = t & 31, wid = t >> 5;
    const int rr = lane >> 2, cc = lane & 3;
    const int b = blockIdx.y, q0 = blockIdx.x * 128;
    const uint32_t sb = smem_to_u32(sbuf);
    const int coff = (wid & 1) << 1;   // chunk-order stagger: 0 or 2

    // ---- Q A-frags into registers (loop-invariant) ----
    uint32_t Qa[8][4];
    {
        const uint4* qsrc = &g_Qp[(((size_t)(b * S_DIM + q0) >> 4) + (size_t)wid) * 256];
        #pragma unroll
        for (int kk = 0; kk < 8; ++kk) {
            uint4 v = qsrc[kk * 32 + lane];
            Qa[kk][0] = v.x; Qa[kk][1] = v.y; Qa[kk][2] = v.z; Qa[kk][3] = v.w;
        }
    }

    float oacc[16][4];
    #pragma unroll
    for (int j = 0; j < 16; ++j)
        #pragma unroll
        for (int q = 0; q < 4; ++q) oacc[j][q] = 0.0f;

    // rsum on tensor pipe: oe = P @ ones (n-col 0 of a virtual tile)
    float oe[4] = {0.0f, 0.0f, 0.0f, 0.0f};
    const uint32_t onesc = (rr == 0) ? 0x3C003C00u : 0u;
    uint32_t bOnes[2] = {onesc, onesc};

    const uint4* kbase = &g_Kp[(size_t)(b * 64) * 2048];
    const uint4* vbase = &g_Vp[(size_t)(b * 64) * 2048];

    // ---- prologue: tiles 0,1 into stages 0,1 ----
    prefetch_tile(sb, kbase, vbase, t);
    CP_COMMIT();
    prefetch_tile(sb + 65536, kbase + 2048, vbase + 2048, t);
    CP_COMMIT();

    int st = 0, stn = 2;   // stage of tile kt; stage for tile kt+2
    for (int kt = 0; kt < 64; ++kt) {
        CP_WAIT1();        // all but newest group done -> tile kt landed
        __syncthreads();   // visibility + overwrite-protection for stage stn

        if (kt < 62)
            prefetch_tile(sb + stn * 65536,
                          kbase + (size_t)(kt + 2) * 2048,
                          vbase + (size_t)(kt + 2) * 2048, t);
        CP_COMMIT();       // commit even when empty: keeps group counting fixed

        const uint4* Ks = sbuf + st * 4096;
        const uint4* Vs = Ks + 2048;

        #pragma unroll
        for (int kq = 0; kq < 4; ++kq) {      // staggered kv chunk order
            const int kkp = (kq + coff) & 3;  // even warps 0123, odd 2301
            float f4[4][4];
            #pragma unroll
            for (int jl = 0; jl < 4; ++jl)
                #pragma unroll
                for (int q = 0; q < 4; ++q) f4[jl][q] = 0.0f;

            #pragma unroll
            for (int jl = 0; jl < 4; ++jl) {
                const int j = 4 * kkp + jl;
                #pragma unroll
                for (int ke = 0; ke < 4; ++ke) {
                    uint4 bv = Ks[j * 128 + ke * 32 + lane];
                    uint32_t b0[2] = {bv.x, bv.y}, b1[2] = {bv.z, bv.w};
                    mma_f16(f4[jl], Qa[2 * ke], b0);
                    mma_f16(f4[jl], Qa[2 * ke + 1], b1);
                }
            }

            uint32_t ph[4][2];
            #pragma unroll
            for (int jl = 0; jl < 4; ++jl) {
                ph[jl][0] = ex2_h2(f4[jl][0], f4[jl][1]);
                ph[jl][1] = ex2_h2(f4[jl][2], f4[jl][3]);
            }
            uint32_t a0[4] = {ph[0][0], ph[0][1], ph[1][0], ph[1][1]};
            uint32_t a1[4] = {ph[2][0], ph[2][1], ph[3][0], ph[3][1]};

            mma_f16(oe, a0, bOnes);
            mma_f16(oe, a1, bOnes);
            #pragma unroll
            for (int je = 0; je < 16; ++je) {
                uint4 bv = Vs[je * 128 + kkp * 32 + lane];
                uint32_t b0[2] = {bv.x, bv.y}, b1[2] = {bv.z, bv.w};
                mma_f16(oacc[je], a0, b0);
                mma_f16(oacc[je], a1, b1);
            }
        }

        st  = (st  == 2) ? 0 : st + 1;
        stn = (stn == 2) ? 0 : stn + 1;
    }

    // ---- row sums in oe[0]/oe[2] of cc==0 lanes; broadcast to quad ----
    const float s0 = __shfl_sync(0xffffffffu, oe[0], lane & 28);
    const float s1 = __shfl_sync(0xffffffffu, oe[2], lane & 28);
    const float inv0 = 1.0f / s0;
    const float inv1 = 1.0f / s1;

    const size_t row0 = (size_t)b * S_DIM + q0 + 16 * wid + rr;
    #pragma unroll
    for (int j = 0; j < 16; ++j) {
        const int e = 8 * j + 2 * cc;
        *(float2*)&out[row0 * E_DIM + e] =
            make_float2(oacc[j][0] * inv0, oacc[j][1] * inv0);
        *(float2*)&out[(row0 + 8) * E_DIM + e] =
            make_float2(oacc[j][2] * inv1, oacc[j][3] * inv1);
    }
}

// ============================== launch =====================================
extern "C" void kernel_launch(void* const* d_in, const int* in_sizes, int n_in,
                              void* d_out, int out_size)
{
    (void)in_sizes; (void)n_in; (void)out_size;
    const float* x  = (const float*)d_in[0];
    const float* Wq = (const float*)d_in[1];
    const float* bq = (const float*)d_in[2];
    const float* Wk = (const float*)d_in[3];
    const float* bk = (const float*)d_in[4];
    const float* Wv = (const float*)d_in[5];
    const float* bv = (const float*)d_in[6];
    float* out = (float*)d_out;

    const int proj_smem = 128 * 132 * 4 + 2048 * 16;   // 100352 B
    const int attn_smem = 3 * 65536;                    // 196608 B

    cudaFuncSetAttribute(proj_kernel, cudaFuncAttributeMaxDynamicSharedMemorySize, proj_smem);
    cudaFuncSetAttribute(attn_mma_kernel, cudaFuncAttributeMaxDynamicSharedMemorySize, attn_smem);

    proj_kernel<<<(B_DIM * S_DIM) / 128, 256, proj_smem>>>(x, Wq, bq, Wk, bk, Wv, bv);

    dim3 ag(S_DIM / 128, B_DIM);
    attn_mma_kernel<<<ag, 256, attn_smem>>>(out);
}

// round 17
// speedup vs baseline: 1.0302x; 1.0302x over previous
#include <cuda_runtime.h>
#include <cuda_fp16.h>
#include <math.h>
#include <stdint.h>

#define B_DIM 2
#define S_DIM 8192
#define E_DIM 128

// fp16 fragment-permuted scratch (uint4 = 8 halves):
// g_Qp: per m-tile (16 q rows): [kk 0..7][lane] -> A-frag m16n8k16 {a0,a1,a2,a3}
// g_Kp: per kv-tile: [j 0..15][kkp 0..3][lane] -> K B-frags (n=kv, k=E)
// g_Vp: per kv-tile: [j(e) 0..15][kkp(kv) 0..3][lane] -> V B-frags (n=E, k=kv)
// g_Wf: CTA-invariant W B-frags for Q,K,V: [which 3][jn 16][kkp 4][lane 32]
__device__ uint4 g_Qp[B_DIM * S_DIM * E_DIM / 8];
__device__ uint4 g_Kp[B_DIM * S_DIM * E_DIM / 8];
__device__ uint4 g_Vp[B_DIM * S_DIM * E_DIM / 8];
__device__ uint4 g_Wf[3 * 2048];

__device__ __forceinline__ uint32_t smem_to_u32(const void* p) {
    uint32_t a;
    asm("{ .reg .u64 t; cvta.to.shared.u64 t, %1; cvt.u32.u64 %0, t; }" : "=r"(a) : "l"(p));
    return a;
}
__device__ __forceinline__ void mma_f16(float* d, const uint32_t* a, const uint32_t* b) {
    asm volatile(
        "mma.sync.aligned.m16n8k16.row.col.f32.f16.f16.f32 "
        "{%0,%1,%2,%3}, {%4,%5,%6,%7}, {%8,%9}, {%0,%1,%2,%3};"
        : "+f"(d[0]), "+f"(d[1]), "+f"(d[2]), "+f"(d[3])
        : "r"(a[0]), "r"(a[1]), "r"(a[2]), "r"(a[3]), "r"(b[0]), "r"(b[1]));
}
__device__ __forceinline__ uint32_t pack_h2(float lo, float hi) {
    __half2 h = __floats2half2_rn(lo, hi);
    return *reinterpret_cast<uint32_t*>(&h);
}
// exp2 on packed fp16 pair: one MUFU op for two values
__device__ __forceinline__ uint32_t ex2_h2(float lo, float hi) {
    __half2 s = __floats2half2_rn(lo, hi);
    uint32_t si = *reinterpret_cast<uint32_t*>(&s);
    uint32_t r;
    asm("ex2.approx.f16x2 %0, %1;" : "=r"(r) : "r"(si));
    return r;
}
__device__ __forceinline__ void cp_async16(uint32_t saddr, const void* g) {
    asm volatile("cp.async.cg.shared.global [%0], [%1], 16;" :: "r"(saddr), "l"(g));
}
#define CP_COMMIT() asm volatile("cp.async.commit_group;" ::: "memory")
#define CP_WAIT1()  asm volatile("cp.async.wait_group 1;" ::: "memory")
#define CP_WAIT0()  asm volatile("cp.async.wait_group 0;" ::: "memory")

// ============ prep: pack W fragments ONCE (CTA-invariant across proj) ======
// grid = 3 (which), 256 threads.
__global__ __launch_bounds__(256) void wpack_kernel(
    const float* __restrict__ Wq, const float* __restrict__ Wk,
    const float* __restrict__ Wv)
{
    const int which = blockIdx.x;
    const float* __restrict__ W = (which == 0) ? Wq : (which == 1) ? Wk : Wv;
    const int t = threadIdx.x;
    const int lane = t & 31, wid = t >> 5;
    const int rr = lane >> 2, cc = lane & 3;

    #pragma unroll
    for (int jj = 0; jj < 2; ++jj) {
        const int jn = 2 * wid + jj;
        const int n0 = 8 * jn + rr;
        #pragma unroll
        for (int kkp = 0; kkp < 4; ++kkp) {
            const int e0 = 32 * kkp + 2 * cc;
            uint4 v;
            v.x = pack_h2(W[n0 * 128 + e0],      W[n0 * 128 + e0 + 1]);
            v.y = pack_h2(W[n0 * 128 + e0 + 8],  W[n0 * 128 + e0 + 9]);
            v.z = pack_h2(W[n0 * 128 + e0 + 16], W[n0 * 128 + e0 + 17]);
            v.w = pack_h2(W[n0 * 128 + e0 + 24], W[n0 * 128 + e0 + 25]);
            g_Wf[which * 2048 + (jn * 4 + kkp) * 32 + lane] = v;
        }
    }
}

// ============ projection: Q,K,V per CTA; W frags streamed via cp.async =====
// grid = (B*S)/128 = 128 CTAs, 256 threads. 3 syncs total.
// SMEM: nat fp32 [0, 67584); Wf3 uint4 [67584, 67584+98304) = 165888 B.
__global__ __launch_bounds__(256) void proj_kernel(
    const float* __restrict__ x,
    const float* __restrict__ bq, const float* __restrict__ bk,
    const float* __restrict__ bvp)
{
    extern __shared__ float sm[];
    float* nat = sm;                             // [s 128][e, stride 132] fp32
    uint4* Wf3 = (uint4*)((char*)sm + 67584);    // [which 3][jn 16][kkp 4][lane 32]

    const int t = threadIdx.x;
    const float kscale = 0.08838834764831845f * 1.4426950408889634f;

    const int row_base = blockIdx.x * 128;
    const int lane = t & 31, wid = t >> 5;
    const int rr = lane >> 2, cc = lane & 3;

    // ---- stream all 3 Wf blocks (96KB) via cp.async (overlaps X pack) ----
    {
        const uint32_t wdst = smem_to_u32(Wf3);
        #pragma unroll
        for (int i = 0; i < 24; ++i) {
            const int s = t + i * 256;
            cp_async16(wdst + s * 16, g_Wf + s);
        }
        CP_COMMIT();
    }

    // ---- X tile -> nat ----
    #pragma unroll
    for (int i = 0; i < 16; ++i) {
        const int f = t + i * 256;
        const int row = f >> 5, c4 = (f & 31) * 4;
        *(float4*)&nat[row * 132 + c4] =
            *(const float4*)&x[(size_t)(row_base + row) * E_DIM + c4];
    }
    __syncthreads();

    // ---- X A-frags into registers ----
    uint32_t Xa[8][4];
    const int r0 = 16 * wid + rr;
    #pragma unroll
    for (int kk = 0; kk < 8; ++kk) {
        const int e0 = 16 * kk + 2 * cc;
        Xa[kk][0] = pack_h2(nat[r0 * 132 + e0],           nat[r0 * 132 + e0 + 1]);
        Xa[kk][1] = pack_h2(nat[(r0 + 8) * 132 + e0],     nat[(r0 + 8) * 132 + e0 + 1]);
        Xa[kk][2] = pack_h2(nat[r0 * 132 + e0 + 8],       nat[r0 * 132 + e0 + 9]);
        Xa[kk][3] = pack_h2(nat[(r0 + 8) * 132 + e0 + 8], nat[(r0 + 8) * 132 + e0 + 9]);
    }
    CP_WAIT0();
    __syncthreads();   // Xa built (nat dead), Wf3 resident

    __half* Vst = (__half*)sm;   // overlays nat
    const int b = row_base / S_DIM, s_in = row_base % S_DIM, kt = s_in >> 7;
    const size_t tbase = (size_t)(b * 64 + kt) * 2048;

    const float* bs[3] = {bq, bk, bvp};

    #pragma unroll 1
    for (int which = 0; which < 3; ++which) {
        const float* __restrict__ bb = bs[which];
        const uint4* Wf = Wf3 + which * 2048;

        #pragma unroll
        for (int jg = 0; jg < 4; ++jg) {
            float f4[4][4];
            #pragma unroll
            for (int jl = 0; jl < 4; ++jl)
                #pragma unroll
                for (int q = 0; q < 4; ++q) f4[jl][q] = 0.0f;

            #pragma unroll
            for (int jl = 0; jl < 4; ++jl) {
                const int jn = 4 * jg + jl;
                #pragma unroll
                for (int kkp = 0; kkp < 4; ++kkp) {
                    uint4 bv = Wf[(jn * 4 + kkp) * 32 + lane];
                    uint32_t b0[2] = {bv.x, bv.y}, b1[2] = {bv.z, bv.w};
                    mma_f16(f4[jl], Xa[2 * kkp], b0);
                    mma_f16(f4[jl], Xa[2 * kkp + 1], b1);
                }
                const float2 bias = *(const float2*)&bb[8 * jn + 2 * cc];
                f4[jl][0] += bias.x; f4[jl][1] += bias.y;
                f4[jl][2] += bias.x; f4[jl][3] += bias.y;
            }

            if (which == 0) {
                #pragma unroll
                for (int jl = 0; jl < 4; ++jl)
                    #pragma unroll
                    for (int q = 0; q < 4; ++q) f4[jl][q] *= kscale;
                const size_t mbase = ((size_t)(row_base >> 4) + (size_t)wid) * 256;
                uint4 v0, v1;
                v0.x = pack_h2(f4[0][0], f4[0][1]);
                v0.y = pack_h2(f4[0][2], f4[0][3]);
                v0.z = pack_h2(f4[1][0], f4[1][1]);
                v0.w = pack_h2(f4[1][2], f4[1][3]);
                g_Qp[mbase + (size_t)(2 * jg) * 32 + lane] = v0;
                v1.x = pack_h2(f4[2][0], f4[2][1]);
                v1.y = pack_h2(f4[2][2], f4[2][3]);
                v1.z = pack_h2(f4[3][0], f4[3][1]);
                v1.w = pack_h2(f4[3][2], f4[3][3]);
                g_Qp[mbase + (size_t)(2 * jg + 1) * 32 + lane] = v1;
            } else if (which == 1) {
                uint4 v0, v1;
                v0.x = pack_h2(f4[0][0], f4[0][1]);
                v0.y = pack_h2(f4[1][0], f4[1][1]);
                v0.z = pack_h2(f4[2][0], f4[2][1]);
                v0.w = pack_h2(f4[3][0], f4[3][1]);
                g_Kp[tbase + (size_t)(2 * wid) * 128 + jg * 32 + lane] = v0;
                v1.x = pack_h2(f4[0][2], f4[0][3]);
                v1.y = pack_h2(f4[1][2], f4[1][3]);
                v1.z = pack_h2(f4[2][2], f4[2][3]);
                v1.w = pack_h2(f4[3][2], f4[3][3]);
                g_Kp[tbase + (size_t)(2 * wid + 1) * 128 + jg * 32 + lane] = v1;
            } else {
                #pragma unroll
                for (int jl = 0; jl < 4; ++jl) {
                    const int e0 = 8 * (4 * jg + jl) + 2 * cc;
                    Vst[e0 * 132 + r0]           = __float2half_rn(f4[jl][0]);
                    Vst[(e0 + 1) * 132 + r0]     = __float2half_rn(f4[jl][1]);
                    Vst[e0 * 132 + r0 + 8]       = __float2half_rn(f4[jl][2]);
                    Vst[(e0 + 1) * 132 + r0 + 8] = __float2half_rn(f4[jl][3]);
                }
            }
        }
    }

    __syncthreads();
    #pragma unroll
    for (int jj = 0; jj < 2; ++jj) {   // V transpose pack from staged [e][s]
        const int j = 2 * wid + jj;
        const int erow = 8 * j + rr;
        #pragma unroll
        for (int kkp = 0; kkp < 4; ++kkp) {
            const int s0 = 32 * kkp + 2 * cc;
            const int s1 = s0 + 16;
            uint4 v;
            v.x = *(const uint32_t*)&Vst[erow * 132 + s0];
            v.y = *(const uint32_t*)&Vst[erow * 132 + s0 + 8];
            v.z = *(const uint32_t*)&Vst[erow * 132 + s1];
            v.w = *(const uint32_t*)&Vst[erow * 132 + s1 + 8];
            g_Vp[tbase + (size_t)j * 128 + kkp * 32 + lane] = v;
        }
    }
}

// ============ fp16 flash attention: 3-stage pipeline, 1 sync/tile =========
// (round-12 kernel, verbatim: 178us, 206 regs, ~94% of crossbar roofline)
__device__ __forceinline__ void prefetch_tile(uint32_t sdst, const uint4* ksrc,
                                              const uint4* vsrc, int t) {
    #pragma unroll
    for (int i = 0; i < 8; ++i) {
        const int s = t + i * 256;
        cp_async16(sdst + s * 16, ksrc + s);
        cp_async16(sdst + 32768 + s * 16, vsrc + s);
    }
}

__global__ __launch_bounds__(256, 1) void attn_mma_kernel(float* __restrict__ out)
{
    extern __shared__ uint4 sbuf[];   // 3 stages x 4096 uint4
    const int t = threadIdx.x;
    const int lane = t & 31, wid = t >> 5;
    const int rr = lane >> 2, cc = lane & 3;
    const int b = blockIdx.y, q0 = blockIdx.x * 128;
    const uint32_t sb = smem_to_u32(sbuf);

    uint32_t Qa[8][4];
    {
        const uint4* qsrc = &g_Qp[(((size_t)(b * S_DIM + q0) >> 4) + (size_t)wid) * 256];
        #pragma unroll
        for (int kk = 0; kk < 8; ++kk) {
            uint4 v = qsrc[kk * 32 + lane];
            Qa[kk][0] = v.x; Qa[kk][1] = v.y; Qa[kk][2] = v.z; Qa[kk][3] = v.w;
        }
    }

    float oacc[16][4];
    #pragma unroll
    for (int j = 0; j < 16; ++j)
        #pragma unroll
        for (int q = 0; q < 4; ++q) oacc[j][q] = 0.0f;

    float oe[4] = {0.0f, 0.0f, 0.0f, 0.0f};
    const uint32_t onesc = (rr == 0) ? 0x3C003C00u : 0u;
    uint32_t bOnes[2] = {onesc, onesc};

    const uint4* kbase = &g_Kp[(size_t)(b * 64) * 2048];
    const uint4* vbase = &g_Vp[(size_t)(b * 64) * 2048];

    prefetch_tile(sb, kbase, vbase, t);
    CP_COMMIT();
    prefetch_tile(sb + 65536, kbase + 2048, vbase + 2048, t);
    CP_COMMIT();

    int st = 0, stn = 2;
    for (int kt = 0; kt < 64; ++kt) {
        CP_WAIT1();
        __syncthreads();

        if (kt < 62)
            prefetch_tile(sb + stn * 65536,
                          kbase + (size_t)(kt + 2) * 2048,
                          vbase + (size_t)(kt + 2) * 2048, t);
        CP_COMMIT();

        const uint4* Ks = sbuf + st * 4096;
        const uint4* Vs = Ks + 2048;

        #pragma unroll
        for (int kkp = 0; kkp < 4; ++kkp) {
            float f4[4][4];
            #pragma unroll
            for (int jl = 0; jl < 4; ++jl)
                #pragma unroll
                for (int q = 0; q < 4; ++q) f4[jl][q] = 0.0f;

            #pragma unroll
            for (int jl = 0; jl < 4; ++jl) {
                const int j = 4 * kkp + jl;
                #pragma unroll
                for (int ke = 0; ke < 4; ++ke) {
                    uint4 bv = Ks[j * 128 + ke * 32 + lane];
                    uint32_t b0[2] = {bv.x, bv.y}, b1[2] = {bv.z, bv.w};
                    mma_f16(f4[jl], Qa[2 * ke], b0);
                    mma_f16(f4[jl], Qa[2 * ke + 1], b1);
                }
            }

            uint32_t ph[4][2];
            #pragma unroll
            for (int jl = 0; jl < 4; ++jl) {
                ph[jl][0] = ex2_h2(f4[jl][0], f4[jl][1]);
                ph[jl][1] = ex2_h2(f4[jl][2], f4[jl][3]);
            }
            uint32_t a0[4] = {ph[0][0], ph[0][1], ph[1][0], ph[1][1]};
            uint32_t a1[4] = {ph[2][0], ph[2][1], ph[3][0], ph[3][1]};

            mma_f16(oe, a0, bOnes);
            mma_f16(oe, a1, bOnes);
            #pragma unroll
            for (int je = 0; je < 16; ++je) {
                uint4 bv = Vs[je * 128 + kkp * 32 + lane];
                uint32_t b0[2] = {bv.x, bv.y}, b1[2] = {bv.z, bv.w};
                mma_f16(oacc[je], a0, b0);
                mma_f16(oacc[je], a1, b1);
            }
        }

        st  = (st  == 2) ? 0 : st + 1;
        stn = (stn == 2) ? 0 : stn + 1;
    }

    const float s0 = __shfl_sync(0xffffffffu, oe[0], lane & 28);
    const float s1 = __shfl_sync(0xffffffffu, oe[2], lane & 28);
    const float inv0 = 1.0f / s0;
    const float inv1 = 1.0f / s1;

    const size_t row0 = (size_t)b * S_DIM + q0 + 16 * wid + rr;
    #pragma unroll
    for (int j = 0; j < 16; ++j) {
        const int e = 8 * j + 2 * cc;
        *(float2*)&out[row0 * E_DIM + e] =
            make_float2(oacc[j][0] * inv0, oacc[j][1] * inv0);
        *(float2*)&out[(row0 + 8) * E_DIM + e] =
            make_float2(oacc[j][2] * inv1, oacc[j][3] * inv1);
    }
}

// ============================== launch =====================================
extern "C" void kernel_launch(void* const* d_in, const int* in_sizes, int n_in,
                              void* d_out, int out_size)
{
    (void)in_sizes; (void)n_in; (void)out_size;
    const float* x  = (const float*)d_in[0];
    const float* Wq = (const float*)d_in[1];
    const float* bq = (const float*)d_in[2];
    const float* Wk = (const float*)d_in[3];
    const float* bk = (const float*)d_in[4];
    const float* Wv = (const float*)d_in[5];
    const float* bv = (const float*)d_in[6];
    float* out = (float*)d_out;

    const int proj_smem = 67584 + 3 * 2048 * 16;   // 165888 B
    const int attn_smem = 3 * 65536;                // 196608 B

    cudaFuncSetAttribute(proj_kernel, cudaFuncAttributeMaxDynamicSharedMemorySize, proj_smem);
    cudaFuncSetAttribute(attn_mma_kernel, cudaFuncAttributeMaxDynamicSharedMemorySize, attn_smem);

    wpack_kernel<<<3, 256>>>(Wq, Wk, Wv);
    proj_kernel<<<(B_DIM * S_DIM) / 128, 256, proj_smem>>>(x, bq, bk, bv);

    dim3 ag(S_DIM / 128, B_DIM);
    attn_mma_kernel<<<ag, 256, attn_smem>>>(out);
}